// round 8
// baseline (speedup 1.0000x reference)
#include <cuda_runtime.h>
#include <cstdint>

// Problem constants
#define RB      128         // batch  (GEMM N)
#define RROUTE  4608        // routes
#define CCO     160         // C*O    (GEMM M)
#define II      8

// K-split
#define NSPLIT  144         // CTAs
#define CHUNK_R 32          // routes per CTA (K=256)
#define CK_R    4           // routes per k-chunk
#define KCH     32          // k per chunk
#define NCH     8
#define NTHREADS 512

// smem: W tile only (x goes registers-direct). Padded row, ldmatrix-friendly.
#define A_ROW   80          // W tile row: 40 fp16 (32 used)
#define BUFB    (CCO * A_ROW)     // 12800 per buffer
#define SMEM_SZ (2 * BUFB)        // 25600 static, double buffered

// partial results [NSPLIT][B][CO]
__device__ float g_partial[NSPLIT * RB * CCO];

// ---------------- helpers ----------------
__device__ __forceinline__ uint32_t smem_u32(const void* p) {
    uint32_t a;
    asm("{ .reg .u64 t; cvta.to.shared.u64 t, %1; cvt.u32.u64 %0, t; }" : "=r"(a) : "l"(p));
    return a;
}
// pack two f32 -> f16x2 (e0 low half, e1 high half)
__device__ __forceinline__ uint32_t packh(float e0, float e1) {
    uint32_t d;
    asm("cvt.rn.f16x2.f32 %0, %1, %2;" : "=r"(d) : "f"(e1), "f"(e0));
    return d;
}
__device__ __forceinline__ void sts64(uint32_t a, uint32_t r0, uint32_t r1) {
    asm volatile("st.shared.v2.b32 [%0], {%1, %2};" :: "r"(a), "r"(r0), "r"(r1) : "memory");
}
__device__ __forceinline__ void ldmx4(uint32_t* r, uint32_t a) {
    asm volatile("ldmatrix.sync.aligned.m8n8.x4.shared.b16 {%0,%1,%2,%3}, [%4];"
                 : "=r"(r[0]), "=r"(r[1]), "=r"(r[2]), "=r"(r[3]) : "r"(a));
}
__device__ __forceinline__ void mma16816(float* d, const uint32_t* a, const uint32_t* b) {
    asm volatile(
        "mma.sync.aligned.m16n8k16.row.col.f32.f16.f16.f32 "
        "{%0,%1,%2,%3}, {%4,%5,%6,%7}, {%8,%9}, {%0,%1,%2,%3};"
        : "+f"(d[0]), "+f"(d[1]), "+f"(d[2]), "+f"(d[3])
        : "r"(a[0]), "r"(a[1]), "r"(a[2]), "r"(a[3]), "r"(b[0]), "r"(b[1]));
}

// ---------------------------------------------------------------------------
// Kernel 1: fp16 mma.sync partial GEMM.
// D[co][b] (per CTA) = sum_{k in 256-slab} W_k[co] * x_k[b]
// 16 warps: 2 (M=co, 80 each) x 8 (N=b, 16 each). Warp tile 80x16 = 5x2 mma tiles.
// W staged in smem (transposed, ldmatrix); x loaded DIRECT from global into
// B fragments (x is K-contiguous, frag = LDG.64 + cvt), prefetched 1 chunk ahead.
// ---------------------------------------------------------------------------
__global__ void __launch_bounds__(NTHREADS, 1)
digitcaps_mma_kernel(const float* __restrict__ x, const float* __restrict__ W)
{
    __shared__ __align__(16) char smem_raw[SMEM_SZ];
    const uint32_t tiles = smem_u32(smem_raw);

    const int tid = threadIdx.x;
    const int lid = tid & 31;
    const int wid = tid >> 5;
    const int wm  = wid & 1;          // M-warp (co)
    const int wn  = wid >> 1;         // N-warp (b)
    const int c0w = wm * 80;
    const int b0w = wn * 16;
    const int r0  = blockIdx.x * CHUNK_R;

    float acc[5][2][4];
#pragma unroll
    for (int mt = 0; mt < 5; mt++)
#pragma unroll
        for (int nt = 0; nt < 2; nt++)
#pragma unroll
            for (int e = 0; e < 4; e++) acc[mt][nt][e] = 0.f;

    // ---- W staging (smem path, as R7) ----
    float4 pw[3];
    auto ldg_w = [&](int ck) {
        const int rc0 = r0 + ck * CK_R;
#pragma unroll
        for (int t = 0; t < 3; t++) {
            int idx = tid + t * NTHREADS;
            if (idx < 1280) {
                int rr = idx / 320, rem = idx - rr * 320;
                int co = rem >> 1, ih = rem & 1;
                pw[t] = __ldg((const float4*)(W + ((size_t)(rc0 + rr) * CCO + co) * II) + ih);
            }
        }
    };
    auto sts_w = [&](uint32_t bb) {
#pragma unroll
        for (int t = 0; t < 3; t++) {
            int idx = tid + t * NTHREADS;
            if (idx < 1280) {
                int rr = idx / 320, rem = idx - rr * 320;
                int co = rem >> 1, ih = rem & 1;
                uint32_t h0 = packh(pw[t].x, pw[t].y), h1 = packh(pw[t].z, pw[t].w);
                sts64(tiles + bb + (uint32_t)(co * A_ROW + rr * 16 + ih * 8), h0, h1);
            }
        }
    };

    // ---- x: direct-to-fragment global loads ----
    // lane needs x[b0w + nt*8 + (lid>>2)][kbase + ks*16 + 2*(lid&3) + {0,1}] and +8
    float2 bx[2][2][2];                 // [nt][ks][half]
    const int bn = lid >> 2;
    const int bk = 2 * (lid & 3);
    auto ldg_b = [&](int ck) {
        const int kbase = (r0 + ck * CK_R) * II;
#pragma unroll
        for (int nt = 0; nt < 2; nt++) {
            const float* p = x + (size_t)(b0w + nt * 8 + bn) * (RROUTE * II) + kbase + bk;
#pragma unroll
            for (int ks = 0; ks < 2; ks++)
#pragma unroll
                for (int h = 0; h < 2; h++)
                    bx[nt][ks][h] = __ldg((const float2*)(p + ks * 16 + h * 8));
        }
    };

    // prologue
    ldg_w(0);
    ldg_b(0);
    sts_w(0);
    __syncthreads();

#pragma unroll 1
    for (int c = 0; c < NCH; c++) {
        const uint32_t bb = (uint32_t)(c & 1) * BUFB;

        // convert this chunk's B frags out of the prefetch registers
        uint32_t bh[2][2][2];
#pragma unroll
        for (int nt = 0; nt < 2; nt++)
#pragma unroll
            for (int ks = 0; ks < 2; ks++)
#pragma unroll
                for (int h = 0; h < 2; h++)
                    bh[nt][ks][h] = packh(bx[nt][ks][h].x, bx[nt][ks][h].y);

        if (c + 1 < NCH) { ldg_w(c + 1); ldg_b(c + 1); }   // long-latency, hidden by mma burst

#pragma unroll
        for (int ks = 0; ks < 2; ks++) {
            const uint32_t k0 = ks * 16;
#pragma unroll
            for (int mt = 0; mt < 5; mt++) {
                uint32_t ah[4];
                ldmx4(ah, tiles + bb
                          + (uint32_t)(c0w + mt * 16 + (lid & 15)) * A_ROW
                          + (k0 + (lid >> 4) * 8) * 2);
#pragma unroll
                for (int nt = 0; nt < 2; nt++)
                    mma16816(acc[mt][nt], ah, bh[nt][ks]);
            }
        }

        if (c + 1 < NCH) {
            sts_w((uint32_t)((c + 1) & 1) * BUFB);   // idle buffer; LDG landed during mmas
            __syncthreads();
        }
    }

    // epilogue: acc -> g_partial[bid][b][co]
    float* op = g_partial + (size_t)blockIdx.x * (RB * CCO);
    const int rl = lid >> 2;
    const int cl = 2 * (lid & 3);
#pragma unroll
    for (int mt = 0; mt < 5; mt++) {
#pragma unroll
        for (int nt = 0; nt < 2; nt++) {
            int co = c0w + mt * 16 + rl;
            int b  = b0w + nt * 8 + cl;
            op[(size_t)b * CCO + co]           = acc[mt][nt][0];
            op[(size_t)(b + 1) * CCO + co]     = acc[mt][nt][1];
            op[(size_t)b * CCO + co + 8]       = acc[mt][nt][2];
            op[(size_t)(b + 1) * CCO + co + 8] = acc[mt][nt][3];
        }
    }
}

// ---------------------------------------------------------------------------
// Kernel 2: reduce partials + squash, v4: one CTA per b (single wave).
// block = 640: ql = co-quad (40), grp = split-group (16 x 9 splits).
// ---------------------------------------------------------------------------
__global__ void __launch_bounds__(640, 1)
digitcaps_squash_kernel(float* __restrict__ out)
{
    __shared__ float4 red[16][40];
    __shared__ float  sv[CCO];

    const int b   = blockIdx.x;
    const int t   = threadIdx.x;
    const int ql  = t % 40;             // co quad (160/4)
    const int grp = t / 40;             // split group 0..15 (9 splits each)

    const float4* p = (const float4*)(g_partial + (size_t)b * CCO) + ql;

    float4 a = make_float4(0.f, 0.f, 0.f, 0.f);
#pragma unroll
    for (int j = 0; j < 9; j++) {
        float4 v = __ldg(p + (size_t)(grp * 9 + j) * (RB * CCO / 4));
        a.x += v.x; a.y += v.y; a.z += v.z; a.w += v.w;
    }
    red[grp][ql] = a;
    __syncthreads();

    if (t < CCO) {
        const int qq = t >> 2, e = t & 3;
        float s = 0.f;
#pragma unroll
        for (int g = 0; g < 16; g++)
            s += ((const float*)&red[g][qq])[e];
        sv[t] = s * (1.0f / (float)RROUTE);
    }
    __syncthreads();

    if (t < CCO) {
        const int base = t & ~15;        // capsule start (16 o's)
        float sq = 0.f;
#pragma unroll
        for (int o = 0; o < 16; o++) {
            float v = sv[base + o];
            sq += v * v;
        }
        float s = sv[t];
        out[(size_t)b * CCO + t] = s * sqrtf(sq) / (1.0f + sq);
    }
}

// ---------------------------------------------------------------------------
extern "C" void kernel_launch(void* const* d_in, const int* in_sizes, int n_in,
                              void* d_out, int out_size)
{
    const float* x = (const float*)d_in[0];   // [128, 4608, 8]
    const float* W = (const float*)d_in[1];   // [1, 4608, 10, 16, 8]
    float* out = (float*)d_out;               // [128, 10, 16]

    digitcaps_mma_kernel<<<NSPLIT, NTHREADS>>>(x, W);
    digitcaps_squash_kernel<<<RB, 640>>>(out);
}

// round 9
// speedup vs baseline: 1.1855x; 1.1855x over previous
#include <cuda_runtime.h>
#include <cstdint>

// Problem constants
#define RB      128         // batch  (GEMM N)
#define RROUTE  4608        // routes
#define CCO     160         // C*O    (GEMM M)
#define II      8

// K-split
#define NSPLIT  144         // CTAs
#define CHUNK_R 32          // routes per CTA (K=256)
#define CK_R    4           // routes per k-chunk
#define KCH     32          // k per chunk
#define NCH     8
#define NTHREADS 512

// smem rows (bytes), padded & 16B aligned, ldmatrix conflict-free
#define A_ROW   80          // W tile row: 40 fp16 (32 used)
#define B_ROW   272         // x tile row: 136 fp16 (128 used)
#define OFF_A   0
#define OFF_B   (CCO * A_ROW)            // 12800
#define BUFB    (OFF_B + KCH * B_ROW)    // 21504 per buffer
#define SMEM_SZ (2 * BUFB)               // 43008 static (double buffered, <48KB)

// partial results, TRANSPOSED for streaming reduction: [B][NSPLIT][CO]
__device__ float g_partial[RB * NSPLIT * CCO];

// ---------------- helpers ----------------
__device__ __forceinline__ uint32_t smem_u32(const void* p) {
    uint32_t a;
    asm("{ .reg .u64 t; cvta.to.shared.u64 t, %1; cvt.u32.u64 %0, t; }" : "=r"(a) : "l"(p));
    return a;
}
// pack two f32 -> f16x2 (e0 low half, e1 high half)
__device__ __forceinline__ uint32_t packh(float e0, float e1) {
    uint32_t d;
    asm("cvt.rn.f16x2.f32 %0, %1, %2;" : "=r"(d) : "f"(e1), "f"(e0));
    return d;
}
__device__ __forceinline__ void sts32(uint32_t a, uint32_t r) {
    asm volatile("st.shared.b32 [%0], %1;" :: "r"(a), "r"(r) : "memory");
}
__device__ __forceinline__ void sts64(uint32_t a, uint32_t r0, uint32_t r1) {
    asm volatile("st.shared.v2.b32 [%0], {%1, %2};" :: "r"(a), "r"(r0), "r"(r1) : "memory");
}
__device__ __forceinline__ void ldmx4(uint32_t* r, uint32_t a) {
    asm volatile("ldmatrix.sync.aligned.m8n8.x4.shared.b16 {%0,%1,%2,%3}, [%4];"
                 : "=r"(r[0]), "=r"(r[1]), "=r"(r[2]), "=r"(r[3]) : "r"(a));
}
__device__ __forceinline__ void ldmx2t(uint32_t* r, uint32_t a) {
    asm volatile("ldmatrix.sync.aligned.m8n8.x2.trans.shared.b16 {%0,%1}, [%2];"
                 : "=r"(r[0]), "=r"(r[1]) : "r"(a));
}
__device__ __forceinline__ void mma16816(float* d, const uint32_t* a, const uint32_t* b) {
    asm volatile(
        "mma.sync.aligned.m16n8k16.row.col.f32.f16.f16.f32 "
        "{%0,%1,%2,%3}, {%4,%5,%6,%7}, {%8,%9}, {%0,%1,%2,%3};"
        : "+f"(d[0]), "+f"(d[1]), "+f"(d[2]), "+f"(d[3])
        : "r"(a[0]), "r"(a[1]), "r"(a[2]), "r"(a[3]), "r"(b[0]), "r"(b[1]));
}
__device__ __forceinline__ float f4elem(const float4& v, int j) {
    switch (j) { case 0: return v.x; case 1: return v.y; case 2: return v.z; default: return v.w; }
}

// ---------------------------------------------------------------------------
// Kernel 1: fp16 mma.sync partial GEMM (R7 configuration, measured 10.8us).
// D[co][b] (per CTA) = sum_{k in 256-slab} W_k[co] * x_k[b]
// 16 warps: 2 (M=co, 80 each) x 8 (N=b, 16 each). Warp tile 80x16 = 5x2 mma tiles.
// Double-buffered 2x21.5KB static smem; one barrier per chunk.
// ---------------------------------------------------------------------------
__global__ void __launch_bounds__(NTHREADS, 1)
digitcaps_mma_kernel(const float* __restrict__ x, const float* __restrict__ W)
{
    __shared__ __align__(16) char smem_raw[SMEM_SZ];
    const uint32_t tiles = smem_u32(smem_raw);

    const int tid = threadIdx.x;
    const int lid = tid & 31;
    const int wid = tid >> 5;
    const int wm  = wid & 1;          // M-warp (co)
    const int wn  = wid >> 1;         // N-warp (b)
    const int c0w = wm * 80;
    const int b0w = wn * 16;
    const int r0  = blockIdx.x * CHUNK_R;

    // x conversion task: b-pair bp, quarter q (k = q*4 + j)
    const int bp = tid >> 3;
    const int q  = tid & 7;

    float acc[5][2][4];
#pragma unroll
    for (int mt = 0; mt < 5; mt++)
#pragma unroll
        for (int nt = 0; nt < 2; nt++)
#pragma unroll
            for (int e = 0; e < 4; e++) acc[mt][nt][e] = 0.f;

    float4 px0, px1, pw[3];

    auto ldg_chunk = [&](int ck) {
        const int rc0 = r0 + ck * CK_R;
        const float4* xb = (const float4*)(x + ((size_t)(2 * bp) * RROUTE + rc0) * II);
        px0 = __ldg(xb + q);
        px1 = __ldg(xb + (RROUTE * II / 4) + q);     // row b+1
#pragma unroll
        for (int t = 0; t < 3; t++) {
            int idx = tid + t * NTHREADS;
            if (idx < 1280) {
                int rr = idx / 320, rem = idx - rr * 320;
                int co = rem >> 1, ih = rem & 1;
                pw[t] = __ldg((const float4*)(W + ((size_t)(rc0 + rr) * CCO + co) * II) + ih);
            }
        }
    };

    auto sts_chunk = [&](uint32_t bb) {
        // x -> B tile [k][b] (transpose during store; fp16 pair (b, b+1) per word)
#pragma unroll
        for (int j = 0; j < 4; j++) {
            uint32_t h = packh(f4elem(px0, j), f4elem(px1, j));
            sts32(tiles + bb + OFF_B + (uint32_t)((q * 4 + j) * B_ROW + 4 * bp), h);
        }
        // W -> A tile [co][k] (natural, k-contiguous)
#pragma unroll
        for (int t = 0; t < 3; t++) {
            int idx = tid + t * NTHREADS;
            if (idx < 1280) {
                int rr = idx / 320, rem = idx - rr * 320;
                int co = rem >> 1, ih = rem & 1;
                uint32_t h0 = packh(pw[t].x, pw[t].y), h1 = packh(pw[t].z, pw[t].w);
                sts64(tiles + bb + OFF_A + (uint32_t)(co * A_ROW + rr * 16 + ih * 8), h0, h1);
            }
        }
    };

    auto compute = [&](uint32_t bb) {
#pragma unroll
        for (int ks = 0; ks < 2; ks++) {
            const uint32_t k0 = ks * 16;
            uint32_t bh[2][2];
            const uint32_t brow = k0 + (lid & 7) + ((lid >> 3) & 1) * 8;
#pragma unroll
            for (int nt = 0; nt < 2; nt++)
                ldmx2t(bh[nt], tiles + bb + OFF_B + brow * B_ROW + (uint32_t)(b0w + nt * 8) * 2);
#pragma unroll
            for (int mt = 0; mt < 5; mt++) {
                uint32_t ah[4];
                ldmx4(ah, tiles + bb + OFF_A
                          + (uint32_t)(c0w + mt * 16 + (lid & 15)) * A_ROW
                          + (k0 + (lid >> 4) * 8) * 2);
#pragma unroll
                for (int nt = 0; nt < 2; nt++)
                    mma16816(acc[mt][nt], ah, bh[nt]);
            }
        }
    };

    // pipeline: prefetch LDG(c+1) in regs over compute(c); STS into idle buffer
    ldg_chunk(0);
    sts_chunk(0);
    __syncthreads();
#pragma unroll 1
    for (int c = 0; c < NCH; c++) {
        const uint32_t bb = (uint32_t)(c & 1) * BUFB;
        if (c + 1 < NCH) ldg_chunk(c + 1);
        compute(bb);
        if (c + 1 < NCH) {
            sts_chunk((uint32_t)((c + 1) & 1) * BUFB);   // other buffer: no wait needed
            __syncthreads();
        }
    }

    // epilogue: acc -> g_partial[b][bid][co]  (transposed layout; L2 merges sectors)
    float* op = g_partial + (size_t)blockIdx.x * CCO;
    const int rl = lid >> 2;
    const int cl = 2 * (lid & 3);
#pragma unroll
    for (int mt = 0; mt < 5; mt++) {
#pragma unroll
        for (int nt = 0; nt < 2; nt++) {
            int co = c0w + mt * 16 + rl;
            int b  = b0w + nt * 8 + cl;
            op[(size_t)b * (NSPLIT * CCO) + co]           = acc[mt][nt][0];
            op[(size_t)(b + 1) * (NSPLIT * CCO) + co]     = acc[mt][nt][1];
            op[(size_t)b * (NSPLIT * CCO) + co + 8]       = acc[mt][nt][2];
            op[(size_t)(b + 1) * (NSPLIT * CCO) + co + 8] = acc[mt][nt][3];
        }
    }
}

// ---------------------------------------------------------------------------
// Kernel 2: reduce partials + squash, v5: streaming layout.
// g_partial is [b][split][co]; each CTA streams one contiguous 92KB b-block.
// block = 640: ql = co-quad (40), grp = split-group (16 x 9 splits).
// Warp reads are 512B contiguous segments, 640B stride between j iterations.
// ---------------------------------------------------------------------------
__global__ void __launch_bounds__(640, 1)
digitcaps_squash_kernel(float* __restrict__ out)
{
    __shared__ float4 red[16][40];
    __shared__ float  sv[CCO];

    const int b   = blockIdx.x;
    const int t   = threadIdx.x;
    const int ql  = t % 40;             // co quad (160/4)
    const int grp = t / 40;             // split group 0..15 (9 splits each)

    const float4* p = (const float4*)(g_partial + (size_t)b * (NSPLIT * CCO)) + ql;

    float4 a = make_float4(0.f, 0.f, 0.f, 0.f);
#pragma unroll
    for (int j = 0; j < 9; j++) {
        float4 v = __ldg(p + (size_t)(grp * 9 + j) * (CCO / 4));
        a.x += v.x; a.y += v.y; a.z += v.z; a.w += v.w;
    }
    red[grp][ql] = a;
    __syncthreads();

    if (t < CCO) {
        const int qq = t >> 2, e = t & 3;
        float s = 0.f;
#pragma unroll
        for (int g = 0; g < 16; g++)
            s += ((const float*)&red[g][qq])[e];
        sv[t] = s * (1.0f / (float)RROUTE);
    }
    __syncthreads();

    if (t < CCO) {
        const int base = t & ~15;        // capsule start (16 o's)
        float sq = 0.f;
#pragma unroll
        for (int o = 0; o < 16; o++) {
            float v = sv[base + o];
            sq += v * v;
        }
        float s = sv[t];
        out[(size_t)b * CCO + t] = s * sqrtf(sq) / (1.0f + sq);
    }
}

// ---------------------------------------------------------------------------
extern "C" void kernel_launch(void* const* d_in, const int* in_sizes, int n_in,
                              void* d_out, int out_size)
{
    const float* x = (const float*)d_in[0];   // [128, 4608, 8]
    const float* W = (const float*)d_in[1];   // [1, 4608, 10, 16, 8]
    float* out = (float*)d_out;               // [128, 10, 16]

    digitcaps_mma_kernel<<<NSPLIT, NTHREADS>>>(x, W);
    digitcaps_squash_kernel<<<RB, 640>>>(out);
}